// round 8
// baseline (speedup 1.0000x reference)
#include <cuda_runtime.h>
#include <cuda_fp16.h>

#define RD 8192

// ---- static device scratch ----
__device__ unsigned d_Ahi[2][512*16*32*4];   // double-buffered h fragments (hi)
__device__ unsigned d_Alo[2][512*16*32*4];   // (lo)
__device__ uint2 d_WGhi[192*16*32];          // chunks: Wh_r,Wh_z,Wh_n,comb_r,comb_z,Wi_n
__device__ uint2 d_WGlo[192*16*32];
__device__ uint2 d_W1hi[16*16*32];
__device__ uint2 d_W1lo[16*16*32];
__device__ uint2 d_W2hi[16*8*32];
__device__ uint2 d_W2lo[16*8*32];
__device__ float d_Mi[768*2];
__device__ float d_ci[768];
__device__ unsigned char d_use[20*64];
__device__ int d_epsMode;

// ---- helpers ----
__device__ __forceinline__ unsigned packsplit(float v0, float v1, unsigned &lo) {
    __half h0 = __float2half(v0);
    __half h1 = __float2half(v1);
    __half l0 = __float2half(v0 - __half2float(h0));
    __half l1 = __float2half(v1 - __half2float(h1));
    lo = ((unsigned)__half_as_ushort(l1) << 16) | (unsigned)__half_as_ushort(l0);
    return ((unsigned)__half_as_ushort(h1) << 16) | (unsigned)__half_as_ushort(h0);
}
__device__ __forceinline__ int fidx(int r, int c, int KT) {
    return (((r >> 4) * KT + (c >> 4)) * 32 + (r & 7) * 4 + ((c & 7) >> 1)) * 4
           + ((r >> 3) & 1) + (((c >> 3) & 1) << 1);
}
__device__ __forceinline__ void mma16816(float (&c)[4], const uint4 a, const uint2 b) {
    asm volatile(
        "mma.sync.aligned.m16n8k16.row.col.f32.f16.f16.f32 "
        "{%0,%1,%2,%3},{%4,%5,%6,%7},{%8,%9},{%0,%1,%2,%3};\n"
        : "+f"(c[0]), "+f"(c[1]), "+f"(c[2]), "+f"(c[3])
        : "r"(a.x), "r"(a.y), "r"(a.z), "r"(a.w), "r"(b.x), "r"(b.y));
}
__device__ __forceinline__ float sigf(float x) {
    return __fdividef(1.f, 1.f + __expf(-x));
}
__device__ __forceinline__ float tanh_f(float x) {
    return 2.f * sigf(2.f * x) - 1.f;
}
__device__ __forceinline__ float eluf(float x) { return x > 0.f ? x : (__expf(x) - 1.f); }

// ---- setup ----
__global__ void s_init() {
    int i = blockIdx.x * 256 + threadIdx.x;
    if (i < 512*16*32*4) { d_Ahi[0][i] = 0u; d_Alo[0][i] = 0u; }
}

__global__ void s_detect(const unsigned char* eps) {
    if (threadIdx.x == 0 && blockIdx.x == 0) {
        int ones3f = 0, nz123 = 0;
        for (int i = 0; i < 768; i++) {
            unsigned char b = eps[i];
            if ((i & 3) == 3 && b == 0x3f) ones3f++;
            if ((i & 3) != 0 && b != 0) nz123++;
        }
        d_epsMode = (ones3f > 0) ? 2 : (nz123 == 0 ? 1 : 0);
    }
}

__global__ void s_pack(const float* __restrict__ wh, const float* __restrict__ wi,
                       const float* __restrict__ w1, const float* __restrict__ w2,
                       const float* __restrict__ ew, const float* __restrict__ eb,
                       const float* __restrict__ bi, const unsigned char* __restrict__ eps) {
    int id = blockIdx.x * 256 + threadIdx.x;
    if (id < 98304) {
        // WG chunk layout: [0,768): Wh r,z,n; [768,1280): Wi+Wh r,z; [1280,1536): Wi n
        int lane = id & 31, kt = (id >> 5) & 15, nt = id >> 9;
        int n = nt * 8 + (lane >> 2);
        const float* sa;
        const float* sb = 0;
        if (n < 768)        { sa = wh + n * 256; }
        else if (n < 1280)  { sa = wi + (n - 768) * 256; sb = wh + (n - 768) * 256; }
        else                { sa = wi + (n - 1280 + 512) * 256; }
        int k0 = kt * 16 + (lane & 3) * 2;
        float v0 = sa[k0]     + (sb ? sb[k0]     : 0.f);
        float v1 = sa[k0+1]   + (sb ? sb[k0+1]   : 0.f);
        float v2 = sa[k0+8]   + (sb ? sb[k0+8]   : 0.f);
        float v3 = sa[k0+9]   + (sb ? sb[k0+9]   : 0.f);
        uint2 H, L;
        H.x = packsplit(v0, v1, L.x);
        H.y = packsplit(v2, v3, L.y);
        d_WGhi[id] = H; d_WGlo[id] = L;
    } else if (id < 106496) {              // W1: [128,256]
        int j = id - 98304;
        int lane = j & 31, kt = (j >> 5) & 15, nt = j >> 9;
        const float* src = w1 + (nt * 8 + (lane >> 2)) * 256;
        int k0 = kt * 16 + (lane & 3) * 2;
        uint2 H, L;
        H.x = packsplit(src[k0],   src[k0+1], L.x);
        H.y = packsplit(src[k0+8], src[k0+9], L.y);
        d_W1hi[j] = H; d_W1lo[j] = L;
    } else if (id < 110592) {              // W2: [128,128]
        int j = id - 106496;
        int lane = j & 31, kt = (j >> 5) & 7, nt = j >> 8;
        const float* src = w2 + (nt * 8 + (lane >> 2)) * 128;
        int k0 = kt * 16 + (lane & 3) * 2;
        uint2 H, L;
        H.x = packsplit(src[k0],   src[k0+1], L.x);
        H.y = packsplit(src[k0+8], src[k0+9], L.y);
        d_W2hi[j] = H; d_W2lo[j] = L;
    } else if (id < 111360) {              // Mi = Wi@embed_w, ci = Wi@embed_b + bi
        int n = id - 110592;
        const float* wr = wi + n * 256;
        float m0 = 0.f, m1 = 0.f, cc = 0.f;
        for (int k = 0; k < 256; k++) {
            float v = wr[k];
            m0 += v * ew[2*k]; m1 += v * ew[2*k+1]; cc += v * eb[k];
        }
        d_Mi[2*n] = m0; d_Mi[2*n+1] = m1; d_ci[n] = cc + bi[n];
    } else if (id < 112640) {              // d_use[t][a]
        int j = id - 111360;
        int t = j >> 6, a = j & 63;
        unsigned char u = 0;
        if (t >= 8) {
            int m = (t - 8) * 64 + a;
            int mode = d_epsMode;
            float v = (mode == 2) ? ((const float*)eps)[m]
                    : (mode == 1) ? (float)((const int*)eps)[m]
                    : (float)eps[m];
            u = (v != 0.f) ? 1 : 0;
        }
        d_use[j] = u;
    }
}

// ---- fused GRU step with cp.async-staged B ----
// B for kt+2 streams into a 3-stage smem ring while kt computes.
// r/z: 1-term; n: 2-term (A-hi + A-lo). A double-buffered in registers.
__global__ void __launch_bounds__(256, 2) k_step(const float* __restrict__ inp,
                                                 const float* __restrict__ bh,
                                                 const float* __restrict__ bi,
                                                 int t, int rb) {
    __shared__ uint2 sB[3][1024];          // 3 stages x (4 chunks x 8 ntiles x 32) uint2

    int am = blockIdx.x, cg = blockIdx.y, rz = blockIdx.z;
    int tid = threadIdx.x;
    int lane = tid & 31, w = tid >> 5;
    int wm = w & 1, wn = w >> 1;           // wn in 0..3
    bool full = d_use[t * 64 + am] != 0;
    const uint4* Ahi_r = (const uint4*)d_Ahi[rb];
    const uint4* Alo_r = (const uint4*)d_Alo[rb];
    unsigned* Ahi_w = d_Ahi[rb ^ 1];
    unsigned* Alo_w = d_Alo[rb ^ 1];

    int nt0 = cg * 8;                      // CTA's first n-tile within each chunk
    int chkA = full ? 3 : 0;               // r chunk
    int chkB = full ? 4 : 1;               // z chunk
    int nchunks = full ? 4 : 3;            // chunk list: {chkA, chkB, 2(, 5)}
    int nxfer = nchunks * 128;             // 16B transfers per stage

    // ---- cp.async stage issuer ----
    // stage layout: group g = cI*8 + local_nt, 32 uint2 per group
    auto issue = [&](int kt, int st) {
        unsigned sbase = (unsigned)__cvta_generic_to_shared(&sB[st][0]);
        #pragma unroll 2
        for (int i = tid; i < nxfer; i += 256) {
            int g = i >> 4, p = i & 15;
            int q = g >> 3, ntl = g & 7;
            int c = (q == 0) ? chkA : (q == 1) ? chkB : (q == 2) ? 2 : 5;
            const char* src = (const char*)d_WGhi
                + (size_t)(((c * 32 + nt0 + ntl) * 16 + kt) * 32) * 8 + p * 16;
            unsigned dst = sbase + g * 256 + p * 16;
            asm volatile("cp.async.cg.shared.global [%0], [%1], 16;\n"
                         :: "r"(dst), "l"(src));
        }
        asm volatile("cp.async.commit_group;\n" ::: "memory");
    };

    int gmt0 = am * 8 + rz * 4 + wm * 2;
    int a0 = (gmt0 * 16) * 32 + lane;
    int a1 = ((gmt0 + 1) * 16) * 32 + lane;

    float acc[2][2][4][4];                 // [mt][nt][gate r,z,nh,ni][4]
#pragma unroll
    for (int i = 0; i < 2; i++)
#pragma unroll
        for (int n = 0; n < 2; n++)
#pragma unroll
            for (int g = 0; g < 4; g++)
#pragma unroll
                for (int q = 0; q < 4; q++) acc[i][n][g][q] = 0.f;

    // prologue: B stages kt=0,1 in flight; A for kt=0 in regs
    issue(0, 0);
    issue(1, 1);
    uint4 ahC0 = Ahi_r[a0], ahC1 = Ahi_r[a1];
    uint4 alC0 = Alo_r[a0], alC1 = Alo_r[a1];

    int soff = (wn * 2) * 32 + lane;       // this warp's base uint2 within a chunk block
    int st = 0;                            // stage holding kt's B

#pragma unroll 2
    for (int kt = 0; kt < 16; kt++) {
        asm volatile("cp.async.wait_group 1;\n" ::: "memory");
        __syncthreads();
        if (kt + 2 < 16) issue(kt + 2, (st + 2 >= 3) ? st - 1 : st + 2);
        else asm volatile("cp.async.commit_group;\n" ::: "memory");

        // A prefetch for kt+1
        int o = ((kt + 1 < 16) ? (kt + 1) : 15) * 32;
        uint4 ahN0 = Ahi_r[a0 + o], ahN1 = Ahi_r[a1 + o];
        uint4 alN0 = Alo_r[a0 + o], alN1 = Alo_r[a1 + o];

        const uint2* Bst = &sB[st][0];
        uint2 Br0 = Bst[soff],        Br1 = Bst[soff + 32];
        uint2 Bz0 = Bst[256 + soff],  Bz1 = Bst[256 + soff + 32];
        uint2 Bn0 = Bst[512 + soff],  Bn1 = Bst[512 + soff + 32];

        mma16816(acc[0][0][0], ahC0, Br0); mma16816(acc[1][0][0], ahC1, Br0);
        mma16816(acc[0][1][0], ahC0, Br1); mma16816(acc[1][1][0], ahC1, Br1);
        mma16816(acc[0][0][1], ahC0, Bz0); mma16816(acc[1][0][1], ahC1, Bz0);
        mma16816(acc[0][1][1], ahC0, Bz1); mma16816(acc[1][1][1], ahC1, Bz1);
        mma16816(acc[0][0][2], ahC0, Bn0); mma16816(acc[1][0][2], ahC1, Bn0);
        mma16816(acc[0][1][2], ahC0, Bn1); mma16816(acc[1][1][2], ahC1, Bn1);
        mma16816(acc[0][0][2], alC0, Bn0); mma16816(acc[1][0][2], alC1, Bn0);
        mma16816(acc[0][1][2], alC0, Bn1); mma16816(acc[1][1][2], alC1, Bn1);
        if (full) {
            uint2 Bi0 = Bst[768 + soff], Bi1 = Bst[768 + soff + 32];
            mma16816(acc[0][0][3], ahC0, Bi0); mma16816(acc[1][0][3], ahC1, Bi0);
            mma16816(acc[0][1][3], ahC0, Bi1); mma16816(acc[1][1][3], ahC1, Bi1);
            mma16816(acc[0][0][3], alC0, Bi0); mma16816(acc[1][0][3], alC1, Bi0);
            mma16816(acc[0][1][3], alC0, Bi1); mma16816(acc[1][1][3], alC1, Bi1);
        }
        ahC0 = ahN0; ahC1 = ahN1; alC0 = alN0; alC1 = alN1;
        st = (st + 1 >= 3) ? 0 : st + 1;
    }

    // ---- gate epilogue (h_old reconstructed from fragments: hi+lo) ----
    int lane4 = lane >> 2;
    float bhr0[2], bhr1[2], bhz0[2], bhz1[2], bhn0[2], bhn1[2];
    float bir0[2], bir1[2], biz0[2], biz1[2], bin0[2], bin1[2];
    float M0a[2][3], M0b[2][3], M1a[2][3], M1b[2][3], C0[2][3], C1[2][3];
    int cc[2];
#pragma unroll
    for (int n = 0; n < 2; n++) {
        int c = (nt0 + wn * 2 + n) * 8 + (lane & 3) * 2;
        cc[n] = c;
        bhr0[n] = bh[c];       bhr1[n] = bh[c + 1];
        bhz0[n] = bh[256 + c]; bhz1[n] = bh[257 + c];
        bhn0[n] = bh[512 + c]; bhn1[n] = bh[513 + c];
        if (full) {
            bir0[n] = bi[c];       bir1[n] = bi[c + 1];
            biz0[n] = bi[256 + c]; biz1[n] = bi[257 + c];
            bin0[n] = bi[512 + c]; bin1[n] = bi[513 + c];
        } else {
#pragma unroll
            for (int g = 0; g < 3; g++) {
                int n0 = g * 256 + c;
                M0a[n][g] = d_Mi[2*n0];     M0b[n][g] = d_Mi[2*n0 + 1];   C0[n][g] = d_ci[n0];
                M1a[n][g] = d_Mi[2*n0 + 2]; M1b[n][g] = d_Mi[2*n0 + 3];   C1[n][g] = d_ci[n0 + 1];
            }
        }
    }
    const unsigned* AhiU = (const unsigned*)Ahi_r;
    const unsigned* AloU = (const unsigned*)Alo_r;

#pragma unroll
    for (int i = 0; i < 2; i++) {
#pragma unroll
        for (int half = 0; half < 2; half++) {
            int r = (gmt0 + i) * 16 + half * 8 + lane4;
            int q0 = half * 2;
            float x0 = 0.f, x1 = 0.f;
            if (!full) {
                int b = r & 127;
                const float* ip = inp + ((b * 64 + am) * 20 + t) * 2;
                x0 = ip[0]; x1 = ip[1];
            }
#pragma unroll
            for (int n = 0; n < 2; n++) {
                int c = cc[n];
                int widx = fidx(r, c, 16);
                unsigned uh = AhiU[widx], ul = AloU[widx];
                __half2 hh = *(__half2*)&uh, hl = *(__half2*)&ul;
                float hox = __half2float(__low2half(hh))  + __half2float(__low2half(hl));
                float hoy = __half2float(__high2half(hh)) + __half2float(__high2half(hl));
                float r0g, r1g, z0g, z1g, n0g, n1g;
                if (full) {
                    r0g = sigf(acc[i][n][0][q0]   + bir0[n] + bhr0[n]);
                    r1g = sigf(acc[i][n][0][q0+1] + bir1[n] + bhr1[n]);
                    z0g = sigf(acc[i][n][1][q0]   + biz0[n] + bhz0[n]);
                    z1g = sigf(acc[i][n][1][q0+1] + biz1[n] + bhz1[n]);
                    n0g = tanh_f(acc[i][n][3][q0]   + bin0[n] + r0g * (acc[i][n][2][q0]   + bhn0[n]));
                    n1g = tanh_f(acc[i][n][3][q0+1] + bin1[n] + r1g * (acc[i][n][2][q0+1] + bhn1[n]));
                } else {
                    float ir0 = x0 * M0a[n][0] + x1 * M0b[n][0] + C0[n][0];
                    float iz0 = x0 * M0a[n][1] + x1 * M0b[n][1] + C0[n][1];
                    float in0 = x0 * M0a[n][2] + x1 * M0b[n][2] + C0[n][2];
                    float ir1 = x0 * M1a[n][0] + x1 * M1b[n][0] + C1[n][0];
                    float iz1 = x0 * M1a[n][1] + x1 * M1b[n][1] + C1[n][1];
                    float in1 = x0 * M1a[n][2] + x1 * M1b[n][2] + C1[n][2];
                    r0g = sigf(ir0 + acc[i][n][0][q0]   + bhr0[n]);
                    r1g = sigf(ir1 + acc[i][n][0][q0+1] + bhr1[n]);
                    z0g = sigf(iz0 + acc[i][n][1][q0]   + bhz0[n]);
                    z1g = sigf(iz1 + acc[i][n][1][q0+1] + bhz1[n]);
                    n0g = tanh_f(in0 + r0g * (acc[i][n][2][q0]   + bhn0[n]));
                    n1g = tanh_f(in1 + r1g * (acc[i][n][2][q0+1] + bhn1[n]));
                }
                float h0 = (1.f - z0g) * n0g + z0g * hox;
                float h1 = (1.f - z1g) * n1g + z1g * hoy;
                unsigned lo, hi = packsplit(h0, h1, lo);
                Ahi_w[widx] = hi; Alo_w[widx] = lo;
            }
        }
    }
}

// ---- fused FC head on 64 rows/CTA: fc1 -> smem frags -> fc2 -> smem -> fc3 ----
extern __shared__ unsigned smem_u[];
__global__ void __launch_bounds__(256) k_fc(const float* __restrict__ b1,
                                            const float* __restrict__ b2,
                                            const float* __restrict__ w3,
                                            const float* __restrict__ b3,
                                            const float* __restrict__ inp,
                                            float* __restrict__ out, int t, int rb) {
    unsigned* sY1hi = smem_u;          // 4096 u32
    unsigned* sY1lo = smem_u + 4096;   // 4096 u32
    float* sy2 = (float*)smem_u;       // 64*132 floats, overwrites after sync
    const uint4* Ahi_r = (const uint4*)d_Ahi[rb];
    const uint4* Alo_r = (const uint4*)d_Alo[rb];

    int lane = threadIdx.x & 31, w = threadIdx.x >> 5;
    int wm = w & 1, wn = w >> 1;
    int lane4 = lane >> 2;
    int agent = blockIdx.x >> 1, halfb = blockIdx.x & 1;
    int gmt0 = agent * 8 + halfb * 4 + wm * 2;

    // ---- fc1 ----
    float acc[2][4][4];
#pragma unroll
    for (int i = 0; i < 2; i++)
#pragma unroll
        for (int j = 0; j < 4; j++)
#pragma unroll
            for (int q = 0; q < 4; q++) acc[i][j][q] = 0.f;
#pragma unroll 2
    for (int kt = 0; kt < 16; kt++) {
        uint4 ah[2], al[2];
#pragma unroll
        for (int i = 0; i < 2; i++) {
            int base = ((gmt0 + i) * 16 + kt) * 32 + lane;
            ah[i] = Ahi_r[base];
            al[i] = Alo_r[base];
        }
#pragma unroll
        for (int j = 0; j < 4; j++) {
            int bb = ((wn * 4 + j) * 16 + kt) * 32 + lane;
            uint2 Bh = d_W1hi[bb], Bl = d_W1lo[bb];
#pragma unroll
            for (int i = 0; i < 2; i++) {
                mma16816(acc[i][j], ah[i], Bh);
                mma16816(acc[i][j], al[i], Bh);
                mma16816(acc[i][j], ah[i], Bl);
            }
        }
    }
#pragma unroll
    for (int i = 0; i < 2; i++)
#pragma unroll
        for (int j = 0; j < 4; j++) {
            int rr = wm * 32 + i * 16 + lane4;          // local row
            int cc = wn * 32 + j * 8 + (lane & 3) * 2;
            float bb0 = b1[cc], bb1 = b1[cc + 1];
            float v0 = eluf(acc[i][j][0] + bb0);
            float v1 = eluf(acc[i][j][1] + bb1);
            unsigned lo, hi = packsplit(v0, v1, lo);
            int widx = fidx(rr, cc, 8);
            sY1hi[widx] = hi; sY1lo[widx] = lo;
            v0 = eluf(acc[i][j][2] + bb0);
            v1 = eluf(acc[i][j][3] + bb1);
            hi = packsplit(v0, v1, lo);
            widx = fidx(rr + 8, cc, 8);
            sY1hi[widx] = hi; sY1lo[widx] = lo;
        }
    __syncthreads();

    // ---- fc2 ----
    float acc2[2][4][4];
#pragma unroll
    for (int i = 0; i < 2; i++)
#pragma unroll
        for (int j = 0; j < 4; j++)
#pragma unroll
            for (int q = 0; q < 4; q++) acc2[i][j][q] = 0.f;
    const uint4* sY1hi4 = (const uint4*)sY1hi;
    const uint4* sY1lo4 = (const uint4*)sY1lo;
#pragma unroll 2
    for (int kt = 0; kt < 8; kt++) {
        uint4 ah[2], al[2];
#pragma unroll
        for (int i = 0; i < 2; i++) {
            int base = ((wm * 2 + i) * 8 + kt) * 32 + lane;
            ah[i] = sY1hi4[base];
            al[i] = sY1lo4[base];
        }
#pragma unroll
        for (int j = 0; j < 4; j++) {
            int bb = ((wn * 4 + j) * 8 + kt) * 32 + lane;
            uint2 Bh = d_W2hi[bb], Bl = d_W2lo[bb];
#pragma unroll
            for (int i = 0; i < 2; i++) {
                mma16816(acc2[i][j], ah[i], Bh);
                mma16816(acc2[i][j], al[i], Bh);
                mma16816(acc2[i][j], ah[i], Bl);
            }
        }
    }
    __syncthreads();   // all sY1 reads done before overwrite with y2

#pragma unroll
    for (int i = 0; i < 2; i++)
#pragma unroll
        for (int j = 0; j < 4; j++) {
            int rr = wm * 32 + i * 16 + lane4;
            int cc = wn * 32 + j * 8 + (lane & 3) * 2;
            float bb0 = b2[cc], bb1 = b2[cc + 1];
            sy2[rr * 132 + cc]           = eluf(acc2[i][j][0] + bb0);
            sy2[rr * 132 + cc + 1]       = eluf(acc2[i][j][1] + bb1);
            sy2[(rr + 8) * 132 + cc]     = eluf(acc2[i][j][2] + bb0);
            sy2[(rr + 8) * 132 + cc + 1] = eluf(acc2[i][j][3] + bb1);
        }
    __syncthreads();

    // ---- fc3 + gt mask ----
    int tid = threadIdx.x;
    if (tid < 128) {
        int rl = tid >> 1, cr = tid & 1;
        const float* wr = w3 + cr * 128;
        float s = b3[cr];
#pragma unroll 8
        for (int k = 0; k < 128; k++) s += sy2[rl * 132 + k] * __ldg(wr + k);
        int b = halfb * 64 + rl;
        float gv = inp[((b * 64 + agent) * 20 + t) * 2 + cr];
        out[((b * 64 + agent) * 12 + (t - 8)) * 2 + cr] = (gv != 0.f) ? s : 0.f;
    }
}

extern "C" void kernel_launch(void* const* d_in, const int* in_sizes, int n_in,
                              void* d_out, int out_size) {
    int sh = (n_in >= 15 && in_sizes[1] <= 4) ? 0 : -1;
    const float* inputs = (const float*)d_in[0];
    const unsigned char* eps = (const unsigned char*)d_in[2 + sh];
    const float* ew = (const float*)d_in[3 + sh];
    const float* eb = (const float*)d_in[4 + sh];
    const float* wi = (const float*)d_in[5 + sh];
    const float* wh = (const float*)d_in[6 + sh];
    const float* bi = (const float*)d_in[7 + sh];
    const float* bh = (const float*)d_in[8 + sh];
    const float* w1 = (const float*)d_in[9 + sh];
    const float* b1 = (const float*)d_in[10 + sh];
    const float* w2 = (const float*)d_in[11 + sh];
    const float* b2 = (const float*)d_in[12 + sh];
    const float* w3 = (const float*)d_in[13 + sh];
    const float* b3 = (const float*)d_in[14 + sh];
    float* out = (float*)d_out;

    // side stream + events for overlapping the FC head with the recurrence
    static cudaStream_t s2 = 0;
    static cudaEvent_t evS = 0, evFc[2] = {0, 0};
    if (!s2) {
        cudaStreamCreateWithFlags(&s2, cudaStreamNonBlocking);
        cudaEventCreateWithFlags(&evS, cudaEventDisableTiming);
        cudaEventCreateWithFlags(&evFc[0], cudaEventDisableTiming);
        cudaEventCreateWithFlags(&evFc[1], cudaEventDisableTiming);
    }

    s_init<<<4096, 256>>>();
    s_detect<<<1, 32>>>(eps);
    s_pack<<<440, 256>>>(wh, wi, w1, w2, ew, eb, bi, eps);

    for (int t = 0; t < 20; t++) {
        // k_step(t) overwrites the buffer k_fc(t-2) reads: enforce ordering
        if (t >= 10) cudaStreamWaitEvent((cudaStream_t)0, evFc[t & 1], 0);
        k_step<<<dim3(64, 4, 2), 256>>>(inputs, bh, bi, t, t & 1);
        if (t >= 8) {
            cudaEventRecord(evS, (cudaStream_t)0);
            cudaStreamWaitEvent(s2, evS, 0);
            k_fc<<<128, 256, 34048, s2>>>(b1, b2, w3, b3, inputs, out, t, (t + 1) & 1);
            cudaEventRecord(evFc[t & 1], s2);
        }
    }
    // join the side stream back before capture/launch ends
    cudaStreamWaitEvent((cudaStream_t)0, evFc[0], 0);
    cudaStreamWaitEvent((cudaStream_t)0, evFc[1], 0);
}

// round 9
// speedup vs baseline: 1.1731x; 1.1731x over previous
#include <cuda_runtime.h>
#include <cuda_fp16.h>

#define RD 8192

// ---- static device scratch ----
__device__ unsigned d_Ahi[2][512*16*32*4];   // double-buffered h fragments (hi)
__device__ unsigned d_Alo[2][512*16*32*4];   // (lo)
// B fragments, paired-nt interleaved layout:
// uint2 index = ((chunk*16 + ntpair)*16 + kt)*64 + lane*2 + (nt&1)
// so one uint4 load yields B for two adjacent n-tiles.
__device__ uint2 d_WGhi[192*16*32];
__device__ uint2 d_W1hi[16*16*32];
__device__ uint2 d_W1lo[16*16*32];
__device__ uint2 d_W2hi[16*8*32];
__device__ uint2 d_W2lo[16*8*32];
__device__ float d_Mi[768*2];
__device__ float d_ci[768];
__device__ unsigned char d_use[20*64];
__device__ int d_epsMode;

// ---- helpers ----
__device__ __forceinline__ unsigned packsplit(float v0, float v1, unsigned &lo) {
    __half h0 = __float2half(v0);
    __half h1 = __float2half(v1);
    __half l0 = __float2half(v0 - __half2float(h0));
    __half l1 = __float2half(v1 - __half2float(h1));
    lo = ((unsigned)__half_as_ushort(l1) << 16) | (unsigned)__half_as_ushort(l0);
    return ((unsigned)__half_as_ushort(h1) << 16) | (unsigned)__half_as_ushort(h0);
}
__device__ __forceinline__ int fidx(int r, int c, int KT) {
    return (((r >> 4) * KT + (c >> 4)) * 32 + (r & 7) * 4 + ((c & 7) >> 1)) * 4
           + ((r >> 3) & 1) + (((c >> 3) & 1) << 1);
}
__device__ __forceinline__ void mma16816(float (&c)[4], const uint4 a, const uint2 b) {
    asm volatile(
        "mma.sync.aligned.m16n8k16.row.col.f32.f16.f16.f32 "
        "{%0,%1,%2,%3},{%4,%5,%6,%7},{%8,%9},{%0,%1,%2,%3};\n"
        : "+f"(c[0]), "+f"(c[1]), "+f"(c[2]), "+f"(c[3])
        : "r"(a.x), "r"(a.y), "r"(a.z), "r"(a.w), "r"(b.x), "r"(b.y));
}
__device__ __forceinline__ float sigf(float x) {
    return __fdividef(1.f, 1.f + __expf(-x));
}
__device__ __forceinline__ float tanh_f(float x) {
    return 2.f * sigf(2.f * x) - 1.f;
}
__device__ __forceinline__ float eluf(float x) { return x > 0.f ? x : (__expf(x) - 1.f); }

// ---- setup ----
__global__ void s_init() {
    int i = blockIdx.x * 256 + threadIdx.x;
    if (i < 512*16*32*4) { d_Ahi[0][i] = 0u; d_Alo[0][i] = 0u; }
}

__global__ void s_detect(const unsigned char* eps) {
    if (threadIdx.x == 0 && blockIdx.x == 0) {
        int ones3f = 0, nz123 = 0;
        for (int i = 0; i < 768; i++) {
            unsigned char b = eps[i];
            if ((i & 3) == 3 && b == 0x3f) ones3f++;
            if ((i & 3) != 0 && b != 0) nz123++;
        }
        d_epsMode = (ones3f > 0) ? 2 : (nz123 == 0 ? 1 : 0);
    }
}

__global__ void s_pack(const float* __restrict__ wh, const float* __restrict__ wi,
                       const float* __restrict__ w1, const float* __restrict__ w2,
                       const float* __restrict__ ew, const float* __restrict__ eb,
                       const float* __restrict__ bi, const unsigned char* __restrict__ eps) {
    int id = blockIdx.x * 256 + threadIdx.x;
    if (id < 98304) {
        // WG chunk layout: [0,768): Wh r,z,n; [768,1280): Wi+Wh r,z; [1280,1536): Wi n
        int lane = id & 31, kt = (id >> 5) & 15, gnt = id >> 9;   // gnt in 0..191
        int n = gnt * 8 + (lane >> 2);
        const float* sa;
        const float* sb = 0;
        if (n < 768)        { sa = wh + n * 256; }
        else if (n < 1280)  { sa = wi + (n - 768) * 256; sb = wh + (n - 768) * 256; }
        else                { sa = wi + (n - 1280 + 512) * 256; }
        int k0 = kt * 16 + (lane & 3) * 2;
        float v0 = sa[k0]     + (sb ? sb[k0]     : 0.f);
        float v1 = sa[k0+1]   + (sb ? sb[k0+1]   : 0.f);
        float v2 = sa[k0+8]   + (sb ? sb[k0+8]   : 0.f);
        float v3 = sa[k0+9]   + (sb ? sb[k0+9]   : 0.f);
        uint2 H;
        unsigned dummy;
        H.x = packsplit(v0, v1, dummy);
        H.y = packsplit(v2, v3, dummy);
        // paired-nt interleaved destination
        int chunk = gnt >> 5, nt = gnt & 31;
        int dest = ((chunk * 16 + (nt >> 1)) * 16 + kt) * 64 + lane * 2 + (nt & 1);
        d_WGhi[dest] = H;
    } else if (id < 106496) {              // W1: [128,256]
        int j = id - 98304;
        int lane = j & 31, kt = (j >> 5) & 15, nt = j >> 9;
        const float* src = w1 + (nt * 8 + (lane >> 2)) * 256;
        int k0 = kt * 16 + (lane & 3) * 2;
        uint2 H, L;
        H.x = packsplit(src[k0],   src[k0+1], L.x);
        H.y = packsplit(src[k0+8], src[k0+9], L.y);
        d_W1hi[j] = H; d_W1lo[j] = L;
    } else if (id < 110592) {              // W2: [128,128]
        int j = id - 106496;
        int lane = j & 31, kt = (j >> 5) & 7, nt = j >> 8;
        const float* src = w2 + (nt * 8 + (lane >> 2)) * 128;
        int k0 = kt * 16 + (lane & 3) * 2;
        uint2 H, L;
        H.x = packsplit(src[k0],   src[k0+1], L.x);
        H.y = packsplit(src[k0+8], src[k0+9], L.y);
        d_W2hi[j] = H; d_W2lo[j] = L;
    } else if (id < 111360) {              // Mi = Wi@embed_w, ci = Wi@embed_b + bi
        int n = id - 110592;
        const float* wr = wi + n * 256;
        float m0 = 0.f, m1 = 0.f, cc = 0.f;
        for (int k = 0; k < 256; k++) {
            float v = wr[k];
            m0 += v * ew[2*k]; m1 += v * ew[2*k+1]; cc += v * eb[k];
        }
        d_Mi[2*n] = m0; d_Mi[2*n+1] = m1; d_ci[n] = cc + bi[n];
    } else if (id < 112640) {              // d_use[t][a]
        int j = id - 111360;
        int t = j >> 6, a = j & 63;
        unsigned char u = 0;
        if (t >= 8) {
            int m = (t - 8) * 64 + a;
            int mode = d_epsMode;
            float v = (mode == 2) ? ((const float*)eps)[m]
                    : (mode == 1) ? (float)((const int*)eps)[m]
                    : (float)eps[m];
            u = (v != 0.f) ? 1 : 0;
        }
        d_use[j] = u;
    }
}

// ---- fused GRU step: warp = 2 m-tiles x 2 n-tiles x {r,z,nh(,ni)} ----
// r/z: 1-term; n: 2-term (A-hi + A-lo). One LDG.128 per gate fetches B for
// BOTH n-tiles (paired layout) -> 7-8 LDG/kt instead of 10-12.
__global__ void __launch_bounds__(256, 2) k_step(const float* __restrict__ inp,
                                                 const float* __restrict__ bh,
                                                 const float* __restrict__ bi,
                                                 int t, int rb) {
    int am = blockIdx.x, cg = blockIdx.y, rz = blockIdx.z;
    int lane = threadIdx.x & 31, w = threadIdx.x >> 5;
    int wm = w & 1, wn = w >> 1;           // wn in 0..3
    bool full = d_use[t * 64 + am] != 0;
    const uint4* Ahi_r = (const uint4*)d_Ahi[rb];
    const uint4* Alo_r = (const uint4*)d_Alo[rb];
    unsigned* Ahi_w = d_Ahi[rb ^ 1];
    unsigned* Alo_w = d_Alo[rb ^ 1];
    const uint4* WG4 = (const uint4*)d_WGhi;

    int ntp = cg * 4 + wn;                 // n-tile PAIR index (16 pairs per chunk)
    int chkR = full ? 3 : 0;
    int chkZ = full ? 4 : 1;
    // uint4 index: ((chk*16 + ntp)*16 + kt)*32 + lane
    int bR = ((chkR * 16 + ntp) * 16) * 32 + lane;
    int bZ = ((chkZ * 16 + ntp) * 16) * 32 + lane;
    int bN = ((2    * 16 + ntp) * 16) * 32 + lane;
    int bI = ((5    * 16 + ntp) * 16) * 32 + lane;

    int gmt0 = am * 8 + rz * 4 + wm * 2;
    int a0 = (gmt0 * 16) * 32 + lane;
    int a1 = ((gmt0 + 1) * 16) * 32 + lane;

    float acc[2][2][4][4];                 // [mt][nt][gate r,z,nh,ni][4]
#pragma unroll
    for (int i = 0; i < 2; i++)
#pragma unroll
        for (int n = 0; n < 2; n++)
#pragma unroll
            for (int g = 0; g < 4; g++)
#pragma unroll
                for (int q = 0; q < 4; q++) acc[i][n][g][q] = 0.f;

    // prologue: A for kt=0
    uint4 ahC0 = Ahi_r[a0], ahC1 = Ahi_r[a1];
    uint4 alC0 = Alo_r[a0], alC1 = Alo_r[a1];

#pragma unroll 4
    for (int kt = 0; kt < 16; kt++) {
        int ob = kt * 32;
        // B loads: one uint4 per gate family covers both n-tiles
        uint4 WR = WG4[bR + ob];
        uint4 WZ = WG4[bZ + ob];
        uint4 WN = WG4[bN + ob];
        uint4 WI;
        if (full) WI = WG4[bI + ob];
        // A prefetch for kt+1
        int o = ((kt + 1 < 16) ? (kt + 1) : 15) * 32;
        uint4 ahN0 = Ahi_r[a0 + o], ahN1 = Ahi_r[a1 + o];
        uint4 alN0 = Alo_r[a0 + o], alN1 = Alo_r[a1 + o];

        uint2 Br0 = make_uint2(WR.x, WR.y), Br1 = make_uint2(WR.z, WR.w);
        uint2 Bz0 = make_uint2(WZ.x, WZ.y), Bz1 = make_uint2(WZ.z, WZ.w);
        uint2 Bn0 = make_uint2(WN.x, WN.y), Bn1 = make_uint2(WN.z, WN.w);

        mma16816(acc[0][0][0], ahC0, Br0); mma16816(acc[1][0][0], ahC1, Br0);
        mma16816(acc[0][1][0], ahC0, Br1); mma16816(acc[1][1][0], ahC1, Br1);
        mma16816(acc[0][0][1], ahC0, Bz0); mma16816(acc[1][0][1], ahC1, Bz0);
        mma16816(acc[0][1][1], ahC0, Bz1); mma16816(acc[1][1][1], ahC1, Bz1);
        mma16816(acc[0][0][2], ahC0, Bn0); mma16816(acc[1][0][2], ahC1, Bn0);
        mma16816(acc[0][1][2], ahC0, Bn1); mma16816(acc[1][1][2], ahC1, Bn1);
        mma16816(acc[0][0][2], alC0, Bn0); mma16816(acc[1][0][2], alC1, Bn0);
        mma16816(acc[0][1][2], alC0, Bn1); mma16816(acc[1][1][2], alC1, Bn1);
        if (full) {
            uint2 Bi0 = make_uint2(WI.x, WI.y), Bi1 = make_uint2(WI.z, WI.w);
            mma16816(acc[0][0][3], ahC0, Bi0); mma16816(acc[1][0][3], ahC1, Bi0);
            mma16816(acc[0][1][3], ahC0, Bi1); mma16816(acc[1][1][3], ahC1, Bi1);
            mma16816(acc[0][0][3], alC0, Bi0); mma16816(acc[1][0][3], alC1, Bi0);
            mma16816(acc[0][1][3], alC0, Bi1); mma16816(acc[1][1][3], alC1, Bi1);
        }
        ahC0 = ahN0; ahC1 = ahN1; alC0 = alN0; alC1 = alN1;
    }

    // ---- gate epilogue (h_old reconstructed from fragments: hi+lo) ----
    int lane4 = lane >> 2;
    int nt0 = cg * 8 + wn * 2;
    float bhr0[2], bhr1[2], bhz0[2], bhz1[2], bhn0[2], bhn1[2];
    float bir0[2], bir1[2], biz0[2], biz1[2], bin0[2], bin1[2];
    float M0a[2][3], M0b[2][3], M1a[2][3], M1b[2][3], C0[2][3], C1[2][3];
    int cc[2];
#pragma unroll
    for (int n = 0; n < 2; n++) {
        int c = (nt0 + n) * 8 + (lane & 3) * 2;
        cc[n] = c;
        bhr0[n] = bh[c];       bhr1[n] = bh[c + 1];
        bhz0[n] = bh[256 + c]; bhz1[n] = bh[257 + c];
        bhn0[n] = bh[512 + c]; bhn1[n] = bh[513 + c];
        if (full) {
            bir0[n] = bi[c];       bir1[n] = bi[c + 1];
            biz0[n] = bi[256 + c]; biz1[n] = bi[257 + c];
            bin0[n] = bi[512 + c]; bin1[n] = bi[513 + c];
        } else {
#pragma unroll
            for (int g = 0; g < 3; g++) {
                int n0 = g * 256 + c;
                M0a[n][g] = d_Mi[2*n0];     M0b[n][g] = d_Mi[2*n0 + 1];   C0[n][g] = d_ci[n0];
                M1a[n][g] = d_Mi[2*n0 + 2]; M1b[n][g] = d_Mi[2*n0 + 3];   C1[n][g] = d_ci[n0 + 1];
            }
        }
    }
    const unsigned* AhiU = (const unsigned*)Ahi_r;
    const unsigned* AloU = (const unsigned*)Alo_r;

#pragma unroll
    for (int i = 0; i < 2; i++) {
#pragma unroll
        for (int half = 0; half < 2; half++) {
            int r = (gmt0 + i) * 16 + half * 8 + lane4;
            int q0 = half * 2;
            float x0 = 0.f, x1 = 0.f;
            if (!full) {
                int b = r & 127;
                const float* ip = inp + ((b * 64 + am) * 20 + t) * 2;
                x0 = ip[0]; x1 = ip[1];
            }
#pragma unroll
            for (int n = 0; n < 2; n++) {
                int c = cc[n];
                int widx = fidx(r, c, 16);
                unsigned uh = AhiU[widx], ul = AloU[widx];
                __half2 hh = *(__half2*)&uh, hl = *(__half2*)&ul;
                float hox = __half2float(__low2half(hh))  + __half2float(__low2half(hl));
                float hoy = __half2float(__high2half(hh)) + __half2float(__high2half(hl));
                float r0g, r1g, z0g, z1g, n0g, n1g;
                if (full) {
                    r0g = sigf(acc[i][n][0][q0]   + bir0[n] + bhr0[n]);
                    r1g = sigf(acc[i][n][0][q0+1] + bir1[n] + bhr1[n]);
                    z0g = sigf(acc[i][n][1][q0]   + biz0[n] + bhz0[n]);
                    z1g = sigf(acc[i][n][1][q0+1] + biz1[n] + bhz1[n]);
                    n0g = tanh_f(acc[i][n][3][q0]   + bin0[n] + r0g * (acc[i][n][2][q0]   + bhn0[n]));
                    n1g = tanh_f(acc[i][n][3][q0+1] + bin1[n] + r1g * (acc[i][n][2][q0+1] + bhn1[n]));
                } else {
                    float ir0 = x0 * M0a[n][0] + x1 * M0b[n][0] + C0[n][0];
                    float iz0 = x0 * M0a[n][1] + x1 * M0b[n][1] + C0[n][1];
                    float in0 = x0 * M0a[n][2] + x1 * M0b[n][2] + C0[n][2];
                    float ir1 = x0 * M1a[n][0] + x1 * M1b[n][0] + C1[n][0];
                    float iz1 = x0 * M1a[n][1] + x1 * M1b[n][1] + C1[n][1];
                    float in1 = x0 * M1a[n][2] + x1 * M1b[n][2] + C1[n][2];
                    r0g = sigf(ir0 + acc[i][n][0][q0]   + bhr0[n]);
                    r1g = sigf(ir1 + acc[i][n][0][q0+1] + bhr1[n]);
                    z0g = sigf(iz0 + acc[i][n][1][q0]   + bhz0[n]);
                    z1g = sigf(iz1 + acc[i][n][1][q0+1] + bhz1[n]);
                    n0g = tanh_f(in0 + r0g * (acc[i][n][2][q0]   + bhn0[n]));
                    n1g = tanh_f(in1 + r1g * (acc[i][n][2][q0+1] + bhn1[n]));
                }
                float h0 = (1.f - z0g) * n0g + z0g * hox;
                float h1 = (1.f - z1g) * n1g + z1g * hoy;
                unsigned lo, hi = packsplit(h0, h1, lo);
                Ahi_w[widx] = hi; Alo_w[widx] = lo;
            }
        }
    }
}

// ---- fused FC head on 64 rows/CTA: fc1 -> smem frags -> fc2 -> smem -> fc3 ----
extern __shared__ unsigned smem_u[];
__global__ void __launch_bounds__(256) k_fc(const float* __restrict__ b1,
                                            const float* __restrict__ b2,
                                            const float* __restrict__ w3,
                                            const float* __restrict__ b3,
                                            const float* __restrict__ inp,
                                            float* __restrict__ out, int t, int rb) {
    unsigned* sY1hi = smem_u;          // 4096 u32
    unsigned* sY1lo = smem_u + 4096;   // 4096 u32
    float* sy2 = (float*)smem_u;       // 64*132 floats, overwrites after sync
    const uint4* Ahi_r = (const uint4*)d_Ahi[rb];
    const uint4* Alo_r = (const uint4*)d_Alo[rb];

    int lane = threadIdx.x & 31, w = threadIdx.x >> 5;
    int wm = w & 1, wn = w >> 1;
    int lane4 = lane >> 2;
    int agent = blockIdx.x >> 1, halfb = blockIdx.x & 1;
    int gmt0 = agent * 8 + halfb * 4 + wm * 2;

    // ---- fc1 ----
    float acc[2][4][4];
#pragma unroll
    for (int i = 0; i < 2; i++)
#pragma unroll
        for (int j = 0; j < 4; j++)
#pragma unroll
            for (int q = 0; q < 4; q++) acc[i][j][q] = 0.f;
#pragma unroll 2
    for (int kt = 0; kt < 16; kt++) {
        uint4 ah[2], al[2];
#pragma unroll
        for (int i = 0; i < 2; i++) {
            int base = ((gmt0 + i) * 16 + kt) * 32 + lane;
            ah[i] = Ahi_r[base];
            al[i] = Alo_r[base];
        }
#pragma unroll
        for (int j = 0; j < 4; j++) {
            int bb = ((wn * 4 + j) * 16 + kt) * 32 + lane;
            uint2 Bh = d_W1hi[bb], Bl = d_W1lo[bb];
#pragma unroll
            for (int i = 0; i < 2; i++) {
                mma16816(acc[i][j], ah[i], Bh);
                mma16816(acc[i][j], al[i], Bh);
                mma16816(acc[i][j], ah[i], Bl);
            }
        }
    }
#pragma unroll
    for (int i = 0; i < 2; i++)
#pragma unroll
        for (int j = 0; j < 4; j++) {
            int rr = wm * 32 + i * 16 + lane4;          // local row
            int cc = wn * 32 + j * 8 + (lane & 3) * 2;
            float bb0 = b1[cc], bb1 = b1[cc + 1];
            float v0 = eluf(acc[i][j][0] + bb0);
            float v1 = eluf(acc[i][j][1] + bb1);
            unsigned lo, hi = packsplit(v0, v1, lo);
            int widx = fidx(rr, cc, 8);
            sY1hi[widx] = hi; sY1lo[widx] = lo;
            v0 = eluf(acc[i][j][2] + bb0);
            v1 = eluf(acc[i][j][3] + bb1);
            hi = packsplit(v0, v1, lo);
            widx = fidx(rr + 8, cc, 8);
            sY1hi[widx] = hi; sY1lo[widx] = lo;
        }
    __syncthreads();

    // ---- fc2 ----
    float acc2[2][4][4];
#pragma unroll
    for (int i = 0; i < 2; i++)
#pragma unroll
        for (int j = 0; j < 4; j++)
#pragma unroll
            for (int q = 0; q < 4; q++) acc2[i][j][q] = 0.f;
    const uint4* sY1hi4 = (const uint4*)sY1hi;
    const uint4* sY1lo4 = (const uint4*)sY1lo;
#pragma unroll 2
    for (int kt = 0; kt < 8; kt++) {
        uint4 ah[2], al[2];
#pragma unroll
        for (int i = 0; i < 2; i++) {
            int base = ((wm * 2 + i) * 8 + kt) * 32 + lane;
            ah[i] = sY1hi4[base];
            al[i] = sY1lo4[base];
        }
#pragma unroll
        for (int j = 0; j < 4; j++) {
            int bb = ((wn * 4 + j) * 8 + kt) * 32 + lane;
            uint2 Bh = d_W2hi[bb], Bl = d_W2lo[bb];
#pragma unroll
            for (int i = 0; i < 2; i++) {
                mma16816(acc2[i][j], ah[i], Bh);
                mma16816(acc2[i][j], al[i], Bh);
                mma16816(acc2[i][j], ah[i], Bl);
            }
        }
    }
    __syncthreads();   // all sY1 reads done before overwrite with y2

#pragma unroll
    for (int i = 0; i < 2; i++)
#pragma unroll
        for (int j = 0; j < 4; j++) {
            int rr = wm * 32 + i * 16 + lane4;
            int cc = wn * 32 + j * 8 + (lane & 3) * 2;
            float bb0 = b2[cc], bb1 = b2[cc + 1];
            sy2[rr * 132 + cc]           = eluf(acc2[i][j][0] + bb0);
            sy2[rr * 132 + cc + 1]       = eluf(acc2[i][j][1] + bb1);
            sy2[(rr + 8) * 132 + cc]     = eluf(acc2[i][j][2] + bb0);
            sy2[(rr + 8) * 132 + cc + 1] = eluf(acc2[i][j][3] + bb1);
        }
    __syncthreads();

    // ---- fc3 + gt mask ----
    int tid = threadIdx.x;
    if (tid < 128) {
        int rl = tid >> 1, cr = tid & 1;
        const float* wr = w3 + cr * 128;
        float s = b3[cr];
#pragma unroll 8
        for (int k = 0; k < 128; k++) s += sy2[rl * 132 + k] * __ldg(wr + k);
        int b = halfb * 64 + rl;
        float gv = inp[((b * 64 + agent) * 20 + t) * 2 + cr];
        out[((b * 64 + agent) * 12 + (t - 8)) * 2 + cr] = (gv != 0.f) ? s : 0.f;
    }
}

extern "C" void kernel_launch(void* const* d_in, const int* in_sizes, int n_in,
                              void* d_out, int out_size) {
    int sh = (n_in >= 15 && in_sizes[1] <= 4) ? 0 : -1;
    const float* inputs = (const float*)d_in[0];
    const unsigned char* eps = (const unsigned char*)d_in[2 + sh];
    const float* ew = (const float*)d_in[3 + sh];
    const float* eb = (const float*)d_in[4 + sh];
    const float* wi = (const float*)d_in[5 + sh];
    const float* wh = (const float*)d_in[6 + sh];
    const float* bi = (const float*)d_in[7 + sh];
    const float* bh = (const float*)d_in[8 + sh];
    const float* w1 = (const float*)d_in[9 + sh];
    const float* b1 = (const float*)d_in[10 + sh];
    const float* w2 = (const float*)d_in[11 + sh];
    const float* b2 = (const float*)d_in[12 + sh];
    const float* w3 = (const float*)d_in[13 + sh];
    const float* b3 = (const float*)d_in[14 + sh];
    float* out = (float*)d_out;

    // side stream + events for overlapping the FC head with the recurrence
    static cudaStream_t s2 = 0;
    static cudaEvent_t evS = 0, evFc[2] = {0, 0};
    if (!s2) {
        cudaStreamCreateWithFlags(&s2, cudaStreamNonBlocking);
        cudaEventCreateWithFlags(&evS, cudaEventDisableTiming);
        cudaEventCreateWithFlags(&evFc[0], cudaEventDisableTiming);
        cudaEventCreateWithFlags(&evFc[1], cudaEventDisableTiming);
    }

    s_init<<<4096, 256>>>();
    s_detect<<<1, 32>>>(eps);
    s_pack<<<440, 256>>>(wh, wi, w1, w2, ew, eb, bi, eps);

    for (int t = 0; t < 20; t++) {
        // k_step(t) overwrites the buffer k_fc(t-2) reads: enforce ordering
        if (t >= 10) cudaStreamWaitEvent((cudaStream_t)0, evFc[t & 1], 0);
        k_step<<<dim3(64, 4, 2), 256>>>(inputs, bh, bi, t, t & 1);
        if (t >= 8) {
            cudaEventRecord(evS, (cudaStream_t)0);
            cudaStreamWaitEvent(s2, evS, 0);
            k_fc<<<128, 256, 34048, s2>>>(b1, b2, w3, b3, inputs, out, t, (t + 1) & 1);
            cudaEventRecord(evFc[t & 1], s2);
        }
    }
    // join the side stream back before capture/launch ends
    cudaStreamWaitEvent((cudaStream_t)0, evFc[0], 0);
    cudaStreamWaitEvent((cudaStream_t)0, evFc[1], 0);
}

// round 10
// speedup vs baseline: 1.2582x; 1.0725x over previous
#include <cuda_runtime.h>
#include <cuda_fp16.h>

// ---- static device scratch ----
// B fragments, paired-nt interleaved layout:
// uint4 index = ((chunk*16 + ntpair)*16 + kt)*32 + lane  -> B for two adjacent n-tiles
__device__ uint2 d_WGhi[192*16*32];
__device__ uint2 d_W1hi[16*16*32];
__device__ uint2 d_W1lo[16*16*32];
__device__ uint2 d_W2hi[16*8*32];
__device__ uint2 d_W2lo[16*8*32];
__device__ float d_Mi[768*2];
__device__ float d_ci[768];
__device__ unsigned char d_use[20*64];
__device__ int d_epsMode;

// ---- helpers ----
__device__ __forceinline__ unsigned packsplit(float v0, float v1, unsigned &lo) {
    __half h0 = __float2half(v0);
    __half h1 = __float2half(v1);
    __half l0 = __float2half(v0 - __half2float(h0));
    __half l1 = __float2half(v1 - __half2float(h1));
    lo = ((unsigned)__half_as_ushort(l1) << 16) | (unsigned)__half_as_ushort(l0);
    return ((unsigned)__half_as_ushort(h1) << 16) | (unsigned)__half_as_ushort(h0);
}
__device__ __forceinline__ int fidx(int r, int c, int KT) {
    return (((r >> 4) * KT + (c >> 4)) * 32 + (r & 7) * 4 + ((c & 7) >> 1)) * 4
           + ((r >> 3) & 1) + (((c >> 3) & 1) << 1);
}
__device__ __forceinline__ void mma16816(float (&c)[4], const uint4 a, const uint2 b) {
    asm volatile(
        "mma.sync.aligned.m16n8k16.row.col.f32.f16.f16.f32 "
        "{%0,%1,%2,%3},{%4,%5,%6,%7},{%8,%9},{%0,%1,%2,%3};\n"
        : "+f"(c[0]), "+f"(c[1]), "+f"(c[2]), "+f"(c[3])
        : "r"(a.x), "r"(a.y), "r"(a.z), "r"(a.w), "r"(b.x), "r"(b.y));
}
__device__ __forceinline__ float sigf(float x) {
    return __fdividef(1.f, 1.f + __expf(-x));
}
__device__ __forceinline__ float tanh_f(float x) {
    return 2.f * sigf(2.f * x) - 1.f;
}
__device__ __forceinline__ float eluf(float x) { return x > 0.f ? x : (__expf(x) - 1.f); }

// ---- setup ----
__global__ void s_detect(const unsigned char* eps) {
    if (threadIdx.x == 0 && blockIdx.x == 0) {
        int ones3f = 0, nz123 = 0;
        for (int i = 0; i < 768; i++) {
            unsigned char b = eps[i];
            if ((i & 3) == 3 && b == 0x3f) ones3f++;
            if ((i & 3) != 0 && b != 0) nz123++;
        }
        d_epsMode = (ones3f > 0) ? 2 : (nz123 == 0 ? 1 : 0);
    }
}

__global__ void s_pack(const float* __restrict__ wh, const float* __restrict__ wi,
                       const float* __restrict__ w1, const float* __restrict__ w2,
                       const float* __restrict__ ew, const float* __restrict__ eb,
                       const float* __restrict__ bi, const unsigned char* __restrict__ eps) {
    int id = blockIdx.x * 256 + threadIdx.x;
    if (id < 98304) {
        // WG chunk layout: [0,768): Wh r,z,n; [768,1280): Wi+Wh r,z; [1280,1536): Wi n
        int lane = id & 31, kt = (id >> 5) & 15, gnt = id >> 9;   // gnt in 0..191
        int n = gnt * 8 + (lane >> 2);
        const float* sa;
        const float* sb = 0;
        if (n < 768)        { sa = wh + n * 256; }
        else if (n < 1280)  { sa = wi + (n - 768) * 256; sb = wh + (n - 768) * 256; }
        else                { sa = wi + (n - 1280 + 512) * 256; }
        int k0 = kt * 16 + (lane & 3) * 2;
        float v0 = sa[k0]     + (sb ? sb[k0]     : 0.f);
        float v1 = sa[k0+1]   + (sb ? sb[k0+1]   : 0.f);
        float v2 = sa[k0+8]   + (sb ? sb[k0+8]   : 0.f);
        float v3 = sa[k0+9]   + (sb ? sb[k0+9]   : 0.f);
        uint2 H;
        unsigned dummy;
        H.x = packsplit(v0, v1, dummy);
        H.y = packsplit(v2, v3, dummy);
        int chunk = gnt >> 5, nt = gnt & 31;
        int dest = ((chunk * 16 + (nt >> 1)) * 16 + kt) * 64 + lane * 2 + (nt & 1);
        d_WGhi[dest] = H;
    } else if (id < 106496) {              // W1: [128,256]
        int j = id - 98304;
        int lane = j & 31, kt = (j >> 5) & 15, nt = j >> 9;
        const float* src = w1 + (nt * 8 + (lane >> 2)) * 256;
        int k0 = kt * 16 + (lane & 3) * 2;
        uint2 H, L;
        H.x = packsplit(src[k0],   src[k0+1], L.x);
        H.y = packsplit(src[k0+8], src[k0+9], L.y);
        d_W1hi[j] = H; d_W1lo[j] = L;
    } else if (id < 110592) {              // W2: [128,128]
        int j = id - 106496;
        int lane = j & 31, kt = (j >> 5) & 7, nt = j >> 8;
        const float* src = w2 + (nt * 8 + (lane >> 2)) * 128;
        int k0 = kt * 16 + (lane & 3) * 2;
        uint2 H, L;
        H.x = packsplit(src[k0],   src[k0+1], L.x);
        H.y = packsplit(src[k0+8], src[k0+9], L.y);
        d_W2hi[j] = H; d_W2lo[j] = L;
    } else if (id < 111360) {              // Mi = Wi@embed_w, ci = Wi@embed_b + bi
        int n = id - 110592;
        const float* wr = wi + n * 256;
        float m0 = 0.f, m1 = 0.f, cc = 0.f;
        for (int k = 0; k < 256; k++) {
            float v = wr[k];
            m0 += v * ew[2*k]; m1 += v * ew[2*k+1]; cc += v * eb[k];
        }
        d_Mi[2*n] = m0; d_Mi[2*n+1] = m1; d_ci[n] = cc + bi[n];
    } else if (id < 112640) {              // d_use[t][a]
        int j = id - 111360;
        int t = j >> 6, a = j & 63;
        unsigned char u = 0;
        if (t >= 8) {
            int m = (t - 8) * 64 + a;
            int mode = d_epsMode;
            float v = (mode == 2) ? ((const float*)eps)[m]
                    : (mode == 1) ? (float)((const int*)eps)[m]
                    : (float)eps[m];
            u = (v != 0.f) ? 1 : 0;
        }
        d_use[j] = u;
    }
}

// =======================================================================
// Persistent fused kernel: CTA = 64 rows (agent, rz-half). h fragments live
// in SMEM for all 20 steps; GRU step + inline FC head; zero global h traffic.
// SMEM: h bufs 2x(32KB hi + 32KB lo) = 128KB @0, FC region 34KB @131072.
// =======================================================================
extern __shared__ unsigned smem_u[];
__global__ void __launch_bounds__(256, 1) k_all(const float* __restrict__ inp,
                                                const float* __restrict__ bh,
                                                const float* __restrict__ bi,
                                                const float* __restrict__ b1,
                                                const float* __restrict__ b2,
                                                const float* __restrict__ w3,
                                                const float* __restrict__ b3,
                                                float* __restrict__ out) {
    uint4* hbuf = (uint4*)smem_u;            // 2 buffers x 4096 uint4 (hi 2048 | lo 2048)
    unsigned* fcmem = smem_u + 32768;        // 34048 bytes

    int am = blockIdx.x >> 1, rz = blockIdx.x & 1;
    int tid = threadIdx.x;
    int lane = tid & 31, w = tid >> 5;
    int wm = w & 1, wn = w >> 1;             // wn in 0..3
    int lane4 = lane >> 2;
    const uint4* WG4 = (const uint4*)d_WGhi;

    // h(0) = 0
    for (int i = tid; i < 4096; i += 256) hbuf[i] = make_uint4(0, 0, 0, 0);
    __syncthreads();

    int curb = 0;
    int lmt0 = wm * 2;                       // warp's first local m-tile (of 4)
    int a0 = (lmt0 * 16) * 32 + lane;        // uint4 idx in hi region for kt=0
    int a1 = a0 + 512;

    for (int t = 0; t < 20; t++) {
        bool full = d_use[t * 64 + am] != 0;
        const uint4* Ahi = hbuf + curb * 4096;
        const uint4* Alo = Ahi + 2048;
        unsigned* Whi = (unsigned*)(hbuf + (curb ^ 1) * 4096);
        unsigned* Wlo = Whi + 8192;
        const unsigned* RdHi = (const unsigned*)Ahi;
        const unsigned* RdLo = (const unsigned*)Alo;

        int chkR = full ? 3 : 0;
        int chkZ = full ? 4 : 1;

        // ---- 4 column-group slices of 64 hidden cols each ----
        for (int cg = 0; cg < 4; cg++) {
            int ntp = cg * 4 + wn;           // n-tile pair (16 per chunk)
            int bR = ((chkR * 16 + ntp) * 16) * 32 + lane;
            int bZ = ((chkZ * 16 + ntp) * 16) * 32 + lane;
            int bN = ((2    * 16 + ntp) * 16) * 32 + lane;
            int bI = ((5    * 16 + ntp) * 16) * 32 + lane;

            float acc[2][2][4][4];
#pragma unroll
            for (int i = 0; i < 2; i++)
#pragma unroll
                for (int n = 0; n < 2; n++)
#pragma unroll
                    for (int g = 0; g < 4; g++)
#pragma unroll
                        for (int q = 0; q < 4; q++) acc[i][n][g][q] = 0.f;

            // prologue: A(0) from SMEM, B(0) from global
            uint4 ahC0 = Ahi[a0], ahC1 = Ahi[a1];
            uint4 alC0 = Alo[a0], alC1 = Alo[a1];
            uint4 WRc = WG4[bR], WZc = WG4[bZ], WNc = WG4[bN];
            uint4 WIc;
            if (full) WIc = WG4[bI];

#pragma unroll 4
            for (int kt = 0; kt < 16; kt++) {
                int on = ((kt + 1 < 16) ? (kt + 1) : 15) * 32;
                // B prefetch for kt+1 (global, ~one-kt distance)
                uint4 WRn = WG4[bR + on], WZn = WG4[bZ + on], WNn = WG4[bN + on];
                uint4 WIn;
                if (full) WIn = WG4[bI + on];
                // A prefetch for kt+1 (SMEM)
                uint4 ahN0 = Ahi[a0 + on], ahN1 = Ahi[a1 + on];
                uint4 alN0 = Alo[a0 + on], alN1 = Alo[a1 + on];

                uint2 Br0 = make_uint2(WRc.x, WRc.y), Br1 = make_uint2(WRc.z, WRc.w);
                uint2 Bz0 = make_uint2(WZc.x, WZc.y), Bz1 = make_uint2(WZc.z, WZc.w);
                uint2 Bn0 = make_uint2(WNc.x, WNc.y), Bn1 = make_uint2(WNc.z, WNc.w);

                mma16816(acc[0][0][0], ahC0, Br0); mma16816(acc[1][0][0], ahC1, Br0);
                mma16816(acc[0][1][0], ahC0, Br1); mma16816(acc[1][1][0], ahC1, Br1);
                mma16816(acc[0][0][1], ahC0, Bz0); mma16816(acc[1][0][1], ahC1, Bz0);
                mma16816(acc[0][1][1], ahC0, Bz1); mma16816(acc[1][1][1], ahC1, Bz1);
                mma16816(acc[0][0][2], ahC0, Bn0); mma16816(acc[1][0][2], ahC1, Bn0);
                mma16816(acc[0][1][2], ahC0, Bn1); mma16816(acc[1][1][2], ahC1, Bn1);
                mma16816(acc[0][0][2], alC0, Bn0); mma16816(acc[1][0][2], alC1, Bn0);
                mma16816(acc[0][1][2], alC0, Bn1); mma16816(acc[1][1][2], alC1, Bn1);
                if (full) {
                    uint2 Bi0 = make_uint2(WIc.x, WIc.y), Bi1 = make_uint2(WIc.z, WIc.w);
                    mma16816(acc[0][0][3], ahC0, Bi0); mma16816(acc[1][0][3], ahC1, Bi0);
                    mma16816(acc[0][1][3], ahC0, Bi1); mma16816(acc[1][1][3], ahC1, Bi1);
                    mma16816(acc[0][0][3], alC0, Bi0); mma16816(acc[1][0][3], alC1, Bi0);
                    mma16816(acc[0][1][3], alC0, Bi1); mma16816(acc[1][1][3], alC1, Bi1);
                    WIc = WIn;
                }
                ahC0 = ahN0; ahC1 = ahN1; alC0 = alN0; alC1 = alN1;
                WRc = WRn; WZc = WZn; WNc = WNn;
            }

            // ---- gate epilogue (h_old from SMEM frags hi+lo) ----
            int nt0 = cg * 8 + wn * 2;
            float bhr0[2], bhr1[2], bhz0[2], bhz1[2], bhn0[2], bhn1[2];
            float bir0[2], bir1[2], biz0[2], biz1[2], bin0[2], bin1[2];
            float M0a[2][3], M0b[2][3], M1a[2][3], M1b[2][3], C0[2][3], C1[2][3];
            int cc[2];
#pragma unroll
            for (int n = 0; n < 2; n++) {
                int c = (nt0 + n) * 8 + (lane & 3) * 2;
                cc[n] = c;
                bhr0[n] = bh[c];       bhr1[n] = bh[c + 1];
                bhz0[n] = bh[256 + c]; bhz1[n] = bh[257 + c];
                bhn0[n] = bh[512 + c]; bhn1[n] = bh[513 + c];
                if (full) {
                    bir0[n] = bi[c];       bir1[n] = bi[c + 1];
                    biz0[n] = bi[256 + c]; biz1[n] = bi[257 + c];
                    bin0[n] = bi[512 + c]; bin1[n] = bi[513 + c];
                } else {
#pragma unroll
                    for (int g = 0; g < 3; g++) {
                        int n0 = g * 256 + c;
                        M0a[n][g] = d_Mi[2*n0];     M0b[n][g] = d_Mi[2*n0 + 1];   C0[n][g] = d_ci[n0];
                        M1a[n][g] = d_Mi[2*n0 + 2]; M1b[n][g] = d_Mi[2*n0 + 3];   C1[n][g] = d_ci[n0 + 1];
                    }
                }
            }

#pragma unroll
            for (int i = 0; i < 2; i++) {
#pragma unroll
                for (int half = 0; half < 2; half++) {
                    int rloc = (lmt0 + i) * 16 + half * 8 + lane4;
                    int q0 = half * 2;
                    float x0 = 0.f, x1 = 0.f;
                    if (!full) {
                        int b = rz * 64 + rloc;
                        const float* ip = inp + ((b * 64 + am) * 20 + t) * 2;
                        x0 = ip[0]; x1 = ip[1];
                    }
#pragma unroll
                    for (int n = 0; n < 2; n++) {
                        int c = cc[n];
                        int widx = fidx(rloc, c, 16);
                        unsigned uh = RdHi[widx], ul = RdLo[widx];
                        __half2 hh = *(__half2*)&uh, hl = *(__half2*)&ul;
                        float hox = __half2float(__low2half(hh))  + __half2float(__low2half(hl));
                        float hoy = __half2float(__high2half(hh)) + __half2float(__high2half(hl));
                        float r0g, r1g, z0g, z1g, n0g, n1g;
                        if (full) {
                            r0g = sigf(acc[i][n][0][q0]   + bir0[n] + bhr0[n]);
                            r1g = sigf(acc[i][n][0][q0+1] + bir1[n] + bhr1[n]);
                            z0g = sigf(acc[i][n][1][q0]   + biz0[n] + bhz0[n]);
                            z1g = sigf(acc[i][n][1][q0+1] + biz1[n] + bhz1[n]);
                            n0g = tanh_f(acc[i][n][3][q0]   + bin0[n] + r0g * (acc[i][n][2][q0]   + bhn0[n]));
                            n1g = tanh_f(acc[i][n][3][q0+1] + bin1[n] + r1g * (acc[i][n][2][q0+1] + bhn1[n]));
                        } else {
                            float ir0 = x0 * M0a[n][0] + x1 * M0b[n][0] + C0[n][0];
                            float iz0 = x0 * M0a[n][1] + x1 * M0b[n][1] + C0[n][1];
                            float in0 = x0 * M0a[n][2] + x1 * M0b[n][2] + C0[n][2];
                            float ir1 = x0 * M1a[n][0] + x1 * M1b[n][0] + C1[n][0];
                            float iz1 = x0 * M1a[n][1] + x1 * M1b[n][1] + C1[n][1];
                            float in1 = x0 * M1a[n][2] + x1 * M1b[n][2] + C1[n][2];
                            r0g = sigf(ir0 + acc[i][n][0][q0]   + bhr0[n]);
                            r1g = sigf(ir1 + acc[i][n][0][q0+1] + bhr1[n]);
                            z0g = sigf(iz0 + acc[i][n][1][q0]   + bhz0[n]);
                            z1g = sigf(iz1 + acc[i][n][1][q0+1] + bhz1[n]);
                            n0g = tanh_f(in0 + r0g * (acc[i][n][2][q0]   + bhn0[n]));
                            n1g = tanh_f(in1 + r1g * (acc[i][n][2][q0+1] + bhn1[n]));
                        }
                        float h0 = (1.f - z0g) * n0g + z0g * hox;
                        float h1 = (1.f - z1g) * n1g + z1g * hoy;
                        unsigned lo, hi = packsplit(h0, h1, lo);
                        Whi[widx] = hi; Wlo[widx] = lo;
                    }
                }
            }
        }
        __syncthreads();       // h(t+1) complete in buffer curb^1
        curb ^= 1;

        // ================= inline FC head (t >= 8) =================
        if (t >= 8) {
            const uint4* Fhi = hbuf + curb * 4096;
            const uint4* Flo = Fhi + 2048;
            unsigned* sY1hi = fcmem;           // 4096 u32
            unsigned* sY1lo = fcmem + 4096;    // 4096 u32
            float* sy2 = (float*)fcmem;        // 64*132 floats (reused after sync)

            // ---- fc1 ----
            float fa[2][4][4];
#pragma unroll
            for (int i = 0; i < 2; i++)
#pragma unroll
                for (int j = 0; j < 4; j++)
#pragma unroll
                    for (int q = 0; q < 4; q++) fa[i][j][q] = 0.f;
#pragma unroll 2
            for (int kt = 0; kt < 16; kt++) {
                uint4 ah[2], al[2];
#pragma unroll
                for (int i = 0; i < 2; i++) {
                    int base = ((lmt0 + i) * 16 + kt) * 32 + lane;
                    ah[i] = Fhi[base];
                    al[i] = Flo[base];
                }
#pragma unroll
                for (int j = 0; j < 4; j++) {
                    int bb = ((wn * 4 + j) * 16 + kt) * 32 + lane;
                    uint2 Bh = d_W1hi[bb], Bl = d_W1lo[bb];
#pragma unroll
                    for (int i = 0; i < 2; i++) {
                        mma16816(fa[i][j], ah[i], Bh);
                        mma16816(fa[i][j], al[i], Bh);
                        mma16816(fa[i][j], ah[i], Bl);
                    }
                }
            }
#pragma unroll
            for (int i = 0; i < 2; i++)
#pragma unroll
                for (int j = 0; j < 4; j++) {
                    int rr = wm * 32 + i * 16 + lane4;
                    int cf = wn * 32 + j * 8 + (lane & 3) * 2;
                    float bb0 = b1[cf], bb1 = b1[cf + 1];
                    float v0 = eluf(fa[i][j][0] + bb0);
                    float v1 = eluf(fa[i][j][1] + bb1);
                    unsigned lo, hi = packsplit(v0, v1, lo);
                    int widx = fidx(rr, cf, 8);
                    sY1hi[widx] = hi; sY1lo[widx] = lo;
                    v0 = eluf(fa[i][j][2] + bb0);
                    v1 = eluf(fa[i][j][3] + bb1);
                    hi = packsplit(v0, v1, lo);
                    widx = fidx(rr + 8, cf, 8);
                    sY1hi[widx] = hi; sY1lo[widx] = lo;
                }
            __syncthreads();

            // ---- fc2 ----
            float fb[2][4][4];
#pragma unroll
            for (int i = 0; i < 2; i++)
#pragma unroll
                for (int j = 0; j < 4; j++)
#pragma unroll
                    for (int q = 0; q < 4; q++) fb[i][j][q] = 0.f;
            const uint4* sY1hi4 = (const uint4*)sY1hi;
            const uint4* sY1lo4 = (const uint4*)sY1lo;
#pragma unroll 2
            for (int kt = 0; kt < 8; kt++) {
                uint4 ah[2], al[2];
#pragma unroll
                for (int i = 0; i < 2; i++) {
                    int base = ((wm * 2 + i) * 8 + kt) * 32 + lane;
                    ah[i] = sY1hi4[base];
                    al[i] = sY1lo4[base];
                }
#pragma unroll
                for (int j = 0; j < 4; j++) {
                    int bb = ((wn * 4 + j) * 8 + kt) * 32 + lane;
                    uint2 Bh = d_W2hi[bb], Bl = d_W2lo[bb];
#pragma unroll
                    for (int i = 0; i < 2; i++) {
                        mma16816(fb[i][j], ah[i], Bh);
                        mma16816(fb[i][j], al[i], Bh);
                        mma16816(fb[i][j], ah[i], Bl);
                    }
                }
            }
            __syncthreads();   // sY1 reads done before overwrite with y2

#pragma unroll
            for (int i = 0; i < 2; i++)
#pragma unroll
                for (int j = 0; j < 4; j++) {
                    int rr = wm * 32 + i * 16 + lane4;
                    int cf = wn * 32 + j * 8 + (lane & 3) * 2;
                    float bb0 = b2[cf], bb1 = b2[cf + 1];
                    sy2[rr * 132 + cf]           = eluf(fb[i][j][0] + bb0);
                    sy2[rr * 132 + cf + 1]       = eluf(fb[i][j][1] + bb1);
                    sy2[(rr + 8) * 132 + cf]     = eluf(fb[i][j][2] + bb0);
                    sy2[(rr + 8) * 132 + cf + 1] = eluf(fb[i][j][3] + bb1);
                }
            __syncthreads();

            // ---- fc3 + gt mask ----
            if (tid < 128) {
                int rl = tid >> 1, cr = tid & 1;
                const float* wr = w3 + cr * 128;
                float s = b3[cr];
#pragma unroll 8
                for (int k = 0; k < 128; k++) s += sy2[rl * 132 + k] * __ldg(wr + k);
                int b = rz * 64 + rl;
                float gv = inp[((b * 64 + am) * 20 + t) * 2 + cr];
                out[((b * 64 + am) * 12 + (t - 8)) * 2 + cr] = (gv != 0.f) ? s : 0.f;
            }
            __syncthreads();   // fc3 reads done before next t's FC writes
        }
    }
}

extern "C" void kernel_launch(void* const* d_in, const int* in_sizes, int n_in,
                              void* d_out, int out_size) {
    int sh = (n_in >= 15 && in_sizes[1] <= 4) ? 0 : -1;
    const float* inputs = (const float*)d_in[0];
    const unsigned char* eps = (const unsigned char*)d_in[2 + sh];
    const float* ew = (const float*)d_in[3 + sh];
    const float* eb = (const float*)d_in[4 + sh];
    const float* wi = (const float*)d_in[5 + sh];
    const float* wh = (const float*)d_in[6 + sh];
    const float* bi = (const float*)d_in[7 + sh];
    const float* bh = (const float*)d_in[8 + sh];
    const float* w1 = (const float*)d_in[9 + sh];
    const float* b1 = (const float*)d_in[10 + sh];
    const float* w2 = (const float*)d_in[11 + sh];
    const float* b2 = (const float*)d_in[12 + sh];
    const float* w3 = (const float*)d_in[13 + sh];
    const float* b3 = (const float*)d_in[14 + sh];
    float* out = (float*)d_out;

    static int smem_set = 0;
    if (!smem_set) {
        cudaFuncSetAttribute(k_all, cudaFuncAttributeMaxDynamicSharedMemorySize, 165120);
        smem_set = 1;
    }

    s_detect<<<1, 32>>>(eps);
    s_pack<<<440, 256>>>(wh, wi, w1, w2, ew, eb, bi, eps);
    k_all<<<128, 256, 165120>>>(inputs, bh, bi, b1, b2, w3, b3, out);
}